// round 8
// baseline (speedup 1.0000x reference)
#include <cuda_runtime.h>
#include <cstdint>

// Problem constants (fixed by the reference setup_inputs)
#define BB     32
#define NN     4096
#define FDIM   128
#define LDH    200            // L*DH floats per agent in hist_feat
#define KK     8
#define APB    256            // agents per block (== blockDim)
#define CHUNKS 16             // blocks per batch
#define CANDS  (CHUNKS * KK)  // 128 candidate keys per batch

#define CH        16                 // columns per pipeline chunk
#define NCH       (FDIM / CH)        // 8 chunks
#define RSTRIDE   5                  // float4 per staged row (20 floats, padded)
#define WARR_F4   (32 * RSTRIDE)     // 160 f4: one array, one stage, one warp
#define WSTAGE_F4 (2 * WARR_F4)      // 320 f4: x+he, one stage (5 KB)
#define WBUF_F4   (2 * WSTAGE_F4)    // 640 f4 per warp (2 stages, 10 KB)
// dyn layout: [warp0 buf]..[warp7 buf][scx 32][scv 32]
#define SMEM_F4    (8 * WBUF_F4 + 64)
#define SMEM_BYTES (SMEM_F4 * 16)    // 82944 B -> 2 blocks/SM

#define KEY_MAX 0xFFFFFFFFFFFFFFFFull
#define FULL    0xffffffffu

__device__ unsigned long long g_cand[BB * CANDS];
__device__ int g_counter[BB];   // zero-init; finisher resets to 0 each call

static __device__ __forceinline__ unsigned long long umin64(unsigned long long a,
                                                            unsigned long long b) {
    return a < b ? a : b;
}

static __device__ __forceinline__ void cp_async16(uint32_t saddr, const void* gptr) {
    asm volatile("cp.async.cg.shared.global [%0], [%1], 16;" :: "r"(saddr), "l"(gptr));
}

// ---------------------------------------------------------------------------
// Fused kernel: warp-private cp.async double buffers with LARGE chunks
// (16 cols -> 5KB groups; one full group outstanding per warp at all times),
// thread-per-agent scoring, hierarchical top-8, fused finisher.
// Keys: (score_bits << 32) | (j-1) -> min-order = (score asc, index asc),
// matching lax.top_k(-score) tie-break semantics.
// ---------------------------------------------------------------------------
__global__ __launch_bounds__(APB, 2)
void fused_kernel(const float* __restrict__ x,   // (B, N, FDIM)
                  const float* __restrict__ hf,  // (B, N, L, DH)
                  const float* __restrict__ he,  // (B, N, FDIM)
                  unsigned long long* __restrict__ cand,
                  float* __restrict__ out)
{
    const int b        = blockIdx.x / CHUNKS;
    const int blkchunk = blockIdx.x % CHUNKS;
    const int t        = threadIdx.x;
    const int warp     = t >> 5;
    const int lane     = t & 31;
    const int j0       = 1 + blkchunk * APB;     // first agent row of block
    const int j0w      = j0 + warp * 32;         // first agent row of warp

    extern __shared__ float4 dyn[];
    float4* wbuf = dyn + warp * WBUF_F4;   // this warp's private buffer
    float4* scx  = dyn + 8 * WBUF_F4;      // center x row (32 f4)
    float4* scv  = scx + 32;               // center embed row (32 f4)
    const uint32_t wbase = (uint32_t)__cvta_generic_to_shared(wbuf);

    __shared__ unsigned long long skeys[8 * KK];
    __shared__ int s_last;
    __shared__ int sel_idx[KK];

    const float4* __restrict__ xb = (const float4*)(x  + (size_t)b * NN * FDIM); // row stride 32 f4
    const float4* __restrict__ ub = (const float4*)(he + (size_t)b * NN * FDIM);

    // ---- stage center rows once ----
    if (t < 32) { scx[t] = xb[t]; scv[t] = ub[t]; }
    __syncthreads();

    // ---- per-thread agent id ----
    const int  j     = j0w + lane;        // == j0 + t
    const bool valid = (j < NN);
    const int  js    = valid ? j : NN - 1;

    // ---- staging: chunk cc (cols [16cc, 16cc+16)) of this warp's 32 rows ----
    auto issue = [&](int cc, int st) {
        const uint32_t sb = wbase + (uint32_t)(st * WSTAGE_F4) * 16u;
        #pragma unroll
        for (int q = 0; q < 4; q++) {
            int i   = lane + 32 * q;      // 0..127 f4 slots (4 per row)
            int row = i >> 2;
            int q4  = i & 3;
            int gr  = j0w + row; if (gr > NN - 1) gr = NN - 1;
            uint32_t soff = (uint32_t)(row * RSTRIDE + q4) * 16u;
            cp_async16(sb + soff, xb + (size_t)gr * 32 + cc * 4 + q4);
            cp_async16(sb + (uint32_t)WARR_F4 * 16u + soff,
                       ub + (size_t)gr * 32 + cc * 4 + q4);
        }
        asm volatile("cp.async.commit_group;");
    };

    // ---- start the pipeline, then do scattered hist_feat work while the
    //      first groups are in flight ----
    issue(0, 0);
    issue(1, 1);

    float vsim;
    {
        const float* h0 = hf + (size_t)b * NN * LDH;
        float2 p048 = *(const float2*)(h0 + 192);
        float2 p049 = *(const float2*)(h0 + 196);
        const float* hj = hf + ((size_t)b * NN + js) * LDH;
        float2 a48 = *(const float2*)(hj + 192);
        float2 a49 = *(const float2*)(hj + 196);

        float d0x = p049.x - p048.x, d0y = p049.y - p048.y;
        float inv0 = 1.0f / fmaxf(sqrtf(d0x*d0x + d0y*d0y), 1e-12f);
        float cdx = d0x * inv0 + 1e-8f;
        float cdy = d0y * inv0 + 1e-8f;
        float cnorm = fmaxf(sqrtf(cdx*cdx + cdy*cdy), 1e-8f);

        float djx = a49.x - a48.x, djy = a49.y - a48.y;
        float invj = 1.0f / fmaxf(sqrtf(djx*djx + djy*djy), 1e-12f);
        float odx = djx * invj + 1e-8f;
        float ody = djy * invj + 1e-8f;
        float vnum = odx*cdx + ody*cdy;
        float vden = fmaxf(sqrtf(odx*odx + ody*ody), 1e-8f) * cnorm;
        vsim = vnum / vden;
    }

    // ---- warp-paced pipelined loop (no __syncthreads inside) ----
    float d2 = 0.0f, tn = 0.0f, uu = 0.0f, vv = 0.0f;

    #pragma unroll
    for (int cc = 0; cc < NCH; cc++) {
        if (cc + 2 < NCH) {
            asm volatile("cp.async.wait_group 1;");   // chunk cc complete
        } else {
            asm volatile("cp.async.wait_group 0;");
        }
        __syncwarp();   // my row's data was copied by other lanes of my warp

        const float4* bx = wbuf + (cc & 1) * WSTAGE_F4 + lane * RSTRIDE;
        const float4* bu = bx + WARR_F4;
        #pragma unroll
        for (int q = 0; q < 4; q++) {
            float4 A = bx[q];
            float4 U = bu[q];
            float4 C = scx[cc * 4 + q];
            float4 V = scv[cc * 4 + q];
            float ex = A.x - C.x, ey = A.y - C.y, ez = A.z - C.z, ew = A.w - C.w;
            d2 += ex*ex + ey*ey + ez*ez + ew*ew;
            tn += U.x*V.x + U.y*V.y + U.z*V.z + U.w*V.w;
            uu += U.x*U.x + U.y*U.y + U.z*U.z + U.w*U.w;
            vv += V.x*V.x + V.y*V.y + V.z*V.z + V.w*V.w;
        }
        __syncwarp();   // all lanes done reading before this stage refills
        if (cc + 2 < NCH) issue(cc + 2, cc & 1);
    }

    // ---- score ----
    const float vnm  = fmaxf(sqrtf(vv), 1e-8f);
    float tsim  = tn / (fmaxf(sqrtf(uu), 1e-8f) * vnm);
    float score = 0.3f * sqrtf(d2)
                + 0.5f * (1.0f - fmaxf(vsim, 0.0f))
                + 0.4f * (1.0f - fmaxf(tsim, 0.0f));
    score = fmaxf(score, 0.0f);   // keep float bit-pattern order-preserving

    unsigned long long mykey = valid
        ? (((unsigned long long)__float_as_uint(score) << 32) | (unsigned int)(j - 1))
        : KEY_MAX;

    // ---- warp top-8: 8 rounds of 64-bit butterfly argmin ----
    unsigned long long sel = KEY_MAX;
    #pragma unroll
    for (int it = 0; it < KK; it++) {
        unsigned long long m = mykey;
        #pragma unroll
        for (int off = 16; off > 0; off >>= 1)
            m = umin64(m, __shfl_xor_sync(FULL, m, off));
        if (mykey == m) mykey = KEY_MAX;   // keys unique -> single winner
        if (lane == it) sel = m;
    }
    if (lane < KK) skeys[warp * KK + lane] = sel;
    __syncthreads();

    // ---- block merge: warp 0 reduces 64 -> 8, writes candidates ----
    if (warp == 0) {
        unsigned long long k0 = skeys[lane];
        unsigned long long k1 = skeys[lane + 32];
        unsigned long long sel2 = KEY_MAX;
        #pragma unroll
        for (int it = 0; it < KK; it++) {
            unsigned long long m = umin64(k0, k1);
            #pragma unroll
            for (int off = 16; off > 0; off >>= 1)
                m = umin64(m, __shfl_xor_sync(FULL, m, off));
            if (k0 == m) k0 = KEY_MAX;
            else if (k1 == m) k1 = KEY_MAX;
            if (lane == it) sel2 = m;
        }
        if (lane < KK)
            cand[((size_t)b * CHUNKS + blkchunk) * KK + lane] = sel2;
    }

    // ---- arrival protocol: last block of this batch merges + gathers ----
    __threadfence();
    __syncthreads();
    if (t == 0) {
        int old = atomicAdd(&g_counter[b], 1);
        s_last = (old == CHUNKS - 1) ? 1 : 0;
    }
    __syncthreads();
    if (!s_last) return;

    __threadfence();   // acquire: see all other blocks' cand writes

    if (t < 32) {
        unsigned long long k[4];
        #pragma unroll
        for (int q = 0; q < 4; q++)
            k[q] = cand[(size_t)b * CANDS + q * 32 + t];

        #pragma unroll
        for (int it = 0; it < KK; it++) {
            unsigned long long m = umin64(umin64(k[0], k[1]), umin64(k[2], k[3]));
            #pragma unroll
            for (int off = 16; off > 0; off >>= 1)
                m = umin64(m, __shfl_xor_sync(FULL, m, off));
            #pragma unroll
            for (int q = 0; q < 4; q++)
                if (k[q] == m) k[q] = KEY_MAX;
            if (t == 0) sel_idx[it] = (int)(unsigned int)(m & 0xFFFFFFFFu);
        }
        if (t == 0) g_counter[b] = 0;   // reset for next graph replay
    }
    __syncthreads();

    // gather: 256 threads = 8 rows x 32 lanes of float4
    {
        const int kk  = t >> 5;
        const int l   = t & 31;
        const int idx = sel_idx[kk];
        float4 val = xb[(size_t)(idx + 1) * 32 + l];
        ((float4*)(out + ((size_t)b * KK + kk) * FDIM))[l] = val;
    }
    if (t < KK)
        out[(size_t)BB * KK * FDIM + b * KK + t] = (float)sel_idx[t];
}

extern "C" void kernel_launch(void* const* d_in, const int* in_sizes, int n_in,
                              void* d_out, int out_size)
{
    const float* x  = (const float*)d_in[0];   // (B, N, FDIM) f32
    const float* hf = (const float*)d_in[1];   // (B, N, L, DH) f32
    const float* he = (const float*)d_in[2];   // (B, N, FDIM) f32
    float* out = (float*)d_out;

    unsigned long long* cand;
    cudaGetSymbolAddress((void**)&cand, g_cand);

    cudaFuncSetAttribute(fused_kernel,
                         cudaFuncAttributeMaxDynamicSharedMemorySize, SMEM_BYTES);

    fused_kernel<<<BB * CHUNKS, APB, SMEM_BYTES>>>(x, hf, he, cand, out);
}

// round 9
// speedup vs baseline: 1.3299x; 1.3299x over previous
#include <cuda_runtime.h>
#include <cstdint>

// Problem constants (fixed by the reference setup_inputs)
#define BB     32
#define NN     4096
#define FDIM   128
#define LDH    200            // L*DH floats per agent in hist_feat
#define KK     8
#define APG    256            // agents per group (== blockDim)
#define GRPS   2              // groups per block
#define BLKS_PER_B 8          // blocks per batch
#define CHUNKS 16             // agent-groups per batch (BLKS_PER_B * GRPS)
#define CANDS  (CHUNKS * KK)  // 128 candidate keys per batch

#define CH       16                 // columns per pipeline chunk
#define NCH      (FDIM / CH)        // 8 chunks
#define RSTRIDE  5                  // float4s per staged row (20 floats, padded)
#define STAGE_F4 (APG * RSTRIDE)    // 1280 float4 per array per stage
// dyn layout: [s0 x][s0 he][s1 x][s1 he][scx 32][scv 32]
#define SMEM_F4    (4 * STAGE_F4 + 64)
#define SMEM_BYTES (SMEM_F4 * 16)   // 82944 B -> 2 blocks/SM

#define KEY_MAX 0xFFFFFFFFFFFFFFFFull
#define FULL    0xffffffffu

__device__ unsigned long long g_cand[BB * CANDS];
__device__ int g_counter[BB];   // zero-init; finisher resets to 0 each call

static __device__ __forceinline__ unsigned long long umin64(unsigned long long a,
                                                            unsigned long long b) {
    return a < b ? a : b;
}

static __device__ __forceinline__ void cp_async16(uint32_t saddr, const void* gptr) {
    asm volatile("cp.async.cg.shared.global [%0], [%1], 16;" :: "r"(saddr), "l"(gptr));
}

// ---------------------------------------------------------------------------
// Fused kernel (single wave): 256 blocks, each handles 512 agents as two
// sequential 256-agent groups using the proven R5 cp.async block pipeline.
// Keys: (score_bits << 32) | (j-1) -> min-order = (score asc, index asc),
// matching lax.top_k(-score) tie-break semantics.
// ---------------------------------------------------------------------------
__global__ __launch_bounds__(APG)
void fused_kernel(const float* __restrict__ x,   // (B, N, FDIM)
                  const float* __restrict__ hf,  // (B, N, L, DH)
                  const float* __restrict__ he,  // (B, N, FDIM)
                  unsigned long long* __restrict__ cand,
                  float* __restrict__ out)
{
    const int b     = blockIdx.x / BLKS_PER_B;
    const int blk   = blockIdx.x % BLKS_PER_B;
    const int t     = threadIdx.x;
    const int warp  = t >> 5;
    const int lane  = t & 31;

    extern __shared__ float4 dyn[];
    float4* scx = dyn + 4 * STAGE_F4;   // center x row (32 f4)
    float4* scv = scx + 32;             // center embed row (32 f4)
    const uint32_t dynbase = (uint32_t)__cvta_generic_to_shared(dyn);

    __shared__ unsigned long long skeys[8 * KK];
    __shared__ int s_last;
    __shared__ int sel_idx[KK];

    const float4* __restrict__ xb = (const float4*)(x  + (size_t)b * NN * FDIM); // row stride 32 f4
    const float4* __restrict__ ub = (const float4*)(he + (size_t)b * NN * FDIM);

    // ---- stage center rows once per block ----
    if (t < 32) { scx[t] = xb[t]; scv[t] = ub[t]; }

    // center direction (uniform loads; compute once)
    const float* h0 = hf + (size_t)b * NN * LDH;
    float2 p048 = *(const float2*)(h0 + 192);
    float2 p049 = *(const float2*)(h0 + 196);
    float d0x = p049.x - p048.x, d0y = p049.y - p048.y;
    float inv0 = 1.0f / fmaxf(sqrtf(d0x*d0x + d0y*d0y), 1e-12f);
    const float cdx = d0x * inv0 + 1e-8f;
    const float cdy = d0y * inv0 + 1e-8f;
    const float cnorm = fmaxf(sqrtf(cdx*cdx + cdy*cdy), 1e-8f);

    #pragma unroll 1
    for (int grp = 0; grp < GRPS; grp++) {
        const int gchunk = blk * GRPS + grp;          // 0..15 within batch
        const int j0     = 1 + gchunk * APG;          // first agent row of group
        const int j      = j0 + t;
        const bool valid = (j < NN);
        const int  js    = valid ? j : NN - 1;

        // ---- staging issue: chunk cc (cols [16cc,16cc+16)) into stage st ----
        auto issue = [&](int cc, int st) {
            const uint32_t sb = dynbase + (uint32_t)(st * 2 * STAGE_F4) * 16u;
            #pragma unroll
            for (int q = 0; q < 4; q++) {
                int i   = t + APG * q;            // 0..1023 f4 slots
                int row = i >> 2;
                int q4  = i & 3;
                int gr  = j0 + row; if (gr > NN - 1) gr = NN - 1;
                uint32_t soff = (uint32_t)(row * RSTRIDE + q4) * 16u;
                cp_async16(sb + soff, xb + (size_t)gr * 32 + cc * 4 + q4);
                cp_async16(sb + (uint32_t)STAGE_F4 * 16u + soff,
                           ub + (size_t)gr * 32 + cc * 4 + q4);
            }
            asm volatile("cp.async.commit_group;");
        };

        issue(0, 0);   // overlap: vsim loads below fly with the first group

        // ---- per-thread velocity similarity ----
        float vsim;
        {
            const float* hj = hf + ((size_t)b * NN + js) * LDH;
            float2 a48 = *(const float2*)(hj + 192);
            float2 a49 = *(const float2*)(hj + 196);
            float djx = a49.x - a48.x, djy = a49.y - a48.y;
            float invj = 1.0f / fmaxf(sqrtf(djx*djx + djy*djy), 1e-12f);
            float odx = djx * invj + 1e-8f;
            float ody = djy * invj + 1e-8f;
            float vnum = odx*cdx + ody*cdy;
            float vden = fmaxf(sqrtf(odx*odx + ody*ody), 1e-8f) * cnorm;
            vsim = vnum / vden;
        }

        // ---- pipelined main loop (R5 structure) ----
        float d2 = 0.0f, tn = 0.0f, uu = 0.0f, vv = 0.0f;

        #pragma unroll
        for (int cc = 0; cc < NCH; cc++) {
            if (cc + 1 < NCH) {
                issue(cc + 1, (cc + 1) & 1);
                asm volatile("cp.async.wait_group 1;");
            } else {
                asm volatile("cp.async.wait_group 0;");
            }
            __syncthreads();   // chunk cc staged everywhere

            const float4* bx = dyn + ((cc & 1) * 2) * STAGE_F4 + t * RSTRIDE;
            const float4* bu = bx + STAGE_F4;
            #pragma unroll
            for (int q = 0; q < 4; q++) {
                float4 A = bx[q];
                float4 U = bu[q];
                float4 C = scx[cc * 4 + q];
                float4 V = scv[cc * 4 + q];
                float ex = A.x - C.x, ey = A.y - C.y, ez = A.z - C.z, ew = A.w - C.w;
                d2 += ex*ex + ey*ey + ez*ez + ew*ew;
                tn += U.x*V.x + U.y*V.y + U.z*V.z + U.w*V.w;
                uu += U.x*U.x + U.y*U.y + U.z*U.z + U.w*U.w;
                vv += V.x*V.x + V.y*V.y + V.z*V.z + V.w*V.w;
            }
            __syncthreads();   // all reads done before this stage refills
        }

        // ---- score ----
        const float vnm  = fmaxf(sqrtf(vv), 1e-8f);
        float tsim  = tn / (fmaxf(sqrtf(uu), 1e-8f) * vnm);
        float score = 0.3f * sqrtf(d2)
                    + 0.5f * (1.0f - fmaxf(vsim, 0.0f))
                    + 0.4f * (1.0f - fmaxf(tsim, 0.0f));
        score = fmaxf(score, 0.0f);   // keep bit-pattern order-preserving

        unsigned long long mykey = valid
            ? (((unsigned long long)__float_as_uint(score) << 32) | (unsigned int)(j - 1))
            : KEY_MAX;

        // ---- warp top-8: 8 rounds of 64-bit butterfly argmin ----
        unsigned long long sel = KEY_MAX;
        #pragma unroll
        for (int it = 0; it < KK; it++) {
            unsigned long long m = mykey;
            #pragma unroll
            for (int off = 16; off > 0; off >>= 1)
                m = umin64(m, __shfl_xor_sync(FULL, m, off));
            if (mykey == m) mykey = KEY_MAX;   // keys unique -> single winner
            if (lane == it) sel = m;
        }
        if (lane < KK) skeys[warp * KK + lane] = sel;
        __syncthreads();

        // ---- block merge: warp 0 reduces 64 -> 8, writes candidates ----
        if (warp == 0) {
            unsigned long long k0 = skeys[lane];
            unsigned long long k1 = skeys[lane + 32];
            unsigned long long sel2 = KEY_MAX;
            #pragma unroll
            for (int it = 0; it < KK; it++) {
                unsigned long long m = umin64(k0, k1);
                #pragma unroll
                for (int off = 16; off > 0; off >>= 1)
                    m = umin64(m, __shfl_xor_sync(FULL, m, off));
                if (k0 == m) k0 = KEY_MAX;
                else if (k1 == m) k1 = KEY_MAX;
                if (lane == it) sel2 = m;
            }
            if (lane < KK)
                cand[((size_t)b * CHUNKS + gchunk) * KK + lane] = sel2;
        }
        __syncthreads();   // skeys reused next group
    }

    // ---- arrival protocol: last block of this batch merges + gathers ----
    __threadfence();
    __syncthreads();
    if (t == 0) {
        int old = atomicAdd(&g_counter[b], 1);
        s_last = (old == BLKS_PER_B - 1) ? 1 : 0;
    }
    __syncthreads();
    if (!s_last) return;

    __threadfence();   // acquire: see all other blocks' cand writes

    if (t < 32) {
        unsigned long long k[4];
        #pragma unroll
        for (int q = 0; q < 4; q++)
            k[q] = cand[(size_t)b * CANDS + q * 32 + t];

        #pragma unroll
        for (int it = 0; it < KK; it++) {
            unsigned long long m = umin64(umin64(k[0], k[1]), umin64(k[2], k[3]));
            #pragma unroll
            for (int off = 16; off > 0; off >>= 1)
                m = umin64(m, __shfl_xor_sync(FULL, m, off));
            #pragma unroll
            for (int q = 0; q < 4; q++)
                if (k[q] == m) k[q] = KEY_MAX;
            if (t == 0) sel_idx[it] = (int)(unsigned int)(m & 0xFFFFFFFFu);
        }
        if (t == 0) g_counter[b] = 0;   // reset for next graph replay
    }
    __syncthreads();

    // gather: 256 threads = 8 rows x 32 lanes of float4
    {
        const int kk  = t >> 5;
        const int l   = t & 31;
        const int idx = sel_idx[kk];
        float4 val = xb[(size_t)(idx + 1) * 32 + l];
        ((float4*)(out + ((size_t)b * KK + kk) * FDIM))[l] = val;
    }
    if (t < KK)
        out[(size_t)BB * KK * FDIM + b * KK + t] = (float)sel_idx[t];
}

extern "C" void kernel_launch(void* const* d_in, const int* in_sizes, int n_in,
                              void* d_out, int out_size)
{
    const float* x  = (const float*)d_in[0];   // (B, N, FDIM) f32
    const float* hf = (const float*)d_in[1];   // (B, N, L, DH) f32
    const float* he = (const float*)d_in[2];   // (B, N, FDIM) f32
    float* out = (float*)d_out;

    unsigned long long* cand;
    cudaGetSymbolAddress((void**)&cand, g_cand);

    cudaFuncSetAttribute(fused_kernel,
                         cudaFuncAttributeMaxDynamicSharedMemorySize, SMEM_BYTES);

    fused_kernel<<<BB * BLKS_PER_B, APG, SMEM_BYTES>>>(x, hf, he, cand, out);
}

// round 10
// speedup vs baseline: 1.4937x; 1.1232x over previous
#include <cuda_runtime.h>
#include <cstdint>

// Problem constants (fixed by the reference setup_inputs)
#define BB     32
#define NN     4096
#define FDIM   128
#define LDH    200
#define KK     8
#define THREADS      256
#define BLKS_PER_B   8
#define ROWS_PER_BLK 512
#define STAGE_ROWS   32
#define NSTAGE       16     // stages per block (16*32 = 512 rows)
#define NBUF         3
#define STAGE_B1     (STAGE_ROWS * FDIM * 4)   // 16384 B per array
#define STAGE_B      (2 * STAGE_B1)            // 32768 B per stage
#define SMEM_BYTES   (NBUF * STAGE_B)          // 98304 B -> 2 blocks/SM

#define CANDS  (BLKS_PER_B * KK)   // 64 candidate keys per batch

#define KEY_MAX 0xFFFFFFFFFFFFFFFFull
#define FULL    0xffffffffu

__device__ unsigned long long g_cand[BB * CANDS];
__device__ int g_counter[BB];   // zero-init; finisher resets to 0 each call

static __device__ __forceinline__ unsigned long long umin64(unsigned long long a,
                                                            unsigned long long b) {
    return a < b ? a : b;
}

// ---------------------------------------------------------------------------
// Fused kernel: cp.async.bulk row-staged 3-deep ring (2 bulk copies per
// stage instead of thousands of cp.asyncs), 8-lane subgroup scoring from
// smem, per-warp top-8, block merge, fused finisher.
// Keys: (score_bits << 32) | (j-1) -> min-order = (score asc, index asc),
// matching lax.top_k(-score) tie-break semantics.
// ---------------------------------------------------------------------------
__global__ __launch_bounds__(THREADS)
void fused_kernel(const float* __restrict__ x,   // (B, N, FDIM)
                  const float* __restrict__ hf,  // (B, N, L, DH)
                  const float* __restrict__ he,  // (B, N, FDIM)
                  unsigned long long* __restrict__ cand,
                  float* __restrict__ out)
{
    const int b   = blockIdx.x / BLKS_PER_B;
    const int blk = blockIdx.x % BLKS_PER_B;
    const int t   = threadIdx.x;
    const int w   = t >> 5;        // warp 0..7
    const int l   = t & 31;        // lane
    const int sg  = l >> 3;        // subgroup 0..3 (row within warp's 4)
    const int sl  = l & 7;         // slice lane 0..7 (16 floats each)
    const int j0  = 1 + blk * ROWS_PER_BLK;

    extern __shared__ char dynsmem[];
    const uint32_t smem_u32 = (uint32_t)__cvta_generic_to_shared(dynsmem);

    __shared__ unsigned long long mbar[NBUF];
    __shared__ unsigned long long skeys[64];
    __shared__ int s_last;
    __shared__ int sel_idx[KK];
    const uint32_t mbar_u32 = (uint32_t)__cvta_generic_to_shared(mbar);

    if (t == 0) {
        #pragma unroll
        for (int s = 0; s < NBUF; s++)
            asm volatile("mbarrier.init.shared.b64 [%0], 1;"
                         :: "r"(mbar_u32 + s * 8) : "memory");
        asm volatile("fence.proxy.async.shared::cta;" ::: "memory");
    }
    __syncthreads();

    const float* xrow = x  + (size_t)b * NN * FDIM;
    const float* urow = he + (size_t)b * NN * FDIM;
    const float4* xb4 = (const float4*)xrow;
    const float4* ub4 = (const float4*)urow;

    // ---- bulk-issue stage cc into buffer cc%3 (single thread) ----
    auto issue = [&](int cc) {
        if (t == 0) {
            const int st   = cc % NBUF;
            const int row0 = j0 + cc * STAGE_ROWS;
            int nrows = NN - row0; if (nrows > STAGE_ROWS) nrows = STAGE_ROWS;
            const uint32_t bytes1 = (uint32_t)nrows * (FDIM * 4);
            const uint32_t mb = mbar_u32 + st * 8;
            asm volatile("mbarrier.arrive.expect_tx.shared.b64 _, [%0], %1;"
                         :: "r"(mb), "r"(2u * bytes1) : "memory");
            const uint32_t d0 = smem_u32 + (uint32_t)st * STAGE_B;
            asm volatile(
                "cp.async.bulk.shared::cta.global.mbarrier::complete_tx::bytes "
                "[%0], [%1], %2, [%3];"
                :: "r"(d0), "l"(xrow + (size_t)row0 * FDIM), "r"(bytes1), "r"(mb)
                : "memory");
            asm volatile(
                "cp.async.bulk.shared::cta.global.mbarrier::complete_tx::bytes "
                "[%0], [%1], %2, [%3];"
                :: "r"(d0 + STAGE_B1), "l"(urow + (size_t)row0 * FDIM), "r"(bytes1), "r"(mb)
                : "memory");
        }
    };

    auto waitbar = [&](int st, int phase) {
        const uint32_t mb = mbar_u32 + st * 8;
        asm volatile(
            "{\n\t.reg .pred P1;\n"
            "W_%=:\n\t"
            "mbarrier.try_wait.parity.acquire.cta.shared::cta.b64 P1, [%0], %1;\n\t"
            "@P1 bra.uni D_%=;\n\t"
            "bra.uni W_%=;\n"
            "D_%=:\n\t}"
            :: "r"(mb), "r"(phase) : "memory");
    };

    issue(0);
    issue(1);

    // ---- centers in registers: this lane's 16-float slice (f4s q*8+sl) ----
    float4 C[4], V[4];
    #pragma unroll
    for (int q = 0; q < 4; q++) { C[q] = xb4[q * 8 + sl]; V[q] = ub4[q * 8 + sl]; }

    float vv = 0.0f;
    #pragma unroll
    for (int q = 0; q < 4; q++)
        vv += V[q].x*V[q].x + V[q].y*V[q].y + V[q].z*V[q].z + V[q].w*V[q].w;
    #pragma unroll
    for (int off = 1; off < 8; off <<= 1)
        vv += __shfl_xor_sync(FULL, vv, off);
    const float vnm = fmaxf(sqrtf(vv), 1e-8f);

    // ---- center direction (uniform) ----
    const float* h0 = hf + (size_t)b * NN * LDH;
    float2 p048 = *(const float2*)(h0 + 192);
    float2 p049 = *(const float2*)(h0 + 196);
    float d0x = p049.x - p048.x, d0y = p049.y - p048.y;
    float inv0 = 1.0f / fmaxf(sqrtf(d0x*d0x + d0y*d0y), 1e-12f);
    const float cdx = d0x * inv0 + 1e-8f;
    const float cdy = d0y * inv0 + 1e-8f;
    const float cnorm = fmaxf(sqrtf(cdx*cdx + cdy*cdy), 1e-8f);

    // ---- vsim precompute: lane l holds agents idx=l (lo) and idx=l+32 (hi)
    //      row(idx) = j0 + (idx>>2)*32 + w*4 + (idx&3) ----
    auto vsim_of = [&](int row) -> float {
        int r = row < NN ? row : NN - 1;
        const float* hj = hf + ((size_t)b * NN + r) * LDH;
        float2 a48 = *(const float2*)(hj + 192);
        float2 a49 = *(const float2*)(hj + 196);
        float djx = a49.x - a48.x, djy = a49.y - a48.y;
        float invj = 1.0f / fmaxf(sqrtf(djx*djx + djy*djy), 1e-12f);
        float odx = djx * invj + 1e-8f;
        float ody = djy * invj + 1e-8f;
        float vnum = odx*cdx + ody*cdy;
        float vden = fmaxf(sqrtf(odx*odx + ody*ody), 1e-8f) * cnorm;
        return vnum / vden;
    };
    const int row_lo = j0 + (l >> 2) * 32 + w * 4 + (l & 3);
    const float vs_lo = vsim_of(row_lo);
    const float vs_hi = vsim_of(row_lo + 256);

    // ---- main loop: 16 row-stages ----
    unsigned long long k0 = KEY_MAX, k1 = KEY_MAX;

    #pragma unroll 2
    for (int cc = 0; cc < NSTAGE; cc++) {
        waitbar(cc % NBUF, (cc / NBUF) & 1);

        // this subgroup's row in the staged buffer
        const float4* sx = (const float4*)(dynsmem + (cc % NBUF) * STAGE_B)
                           + (w * 4 + sg) * (FDIM / 4);
        const float4* su = (const float4*)(dynsmem + (cc % NBUF) * STAGE_B + STAGE_B1)
                           + (w * 4 + sg) * (FDIM / 4);

        float d2 = 0.0f, tn = 0.0f, uu = 0.0f;
        #pragma unroll
        for (int q = 0; q < 4; q++) {
            float4 A = sx[q * 8 + sl];
            float4 U = su[q * 8 + sl];
            float ex = A.x - C[q].x, ey = A.y - C[q].y,
                  ez = A.z - C[q].z, ew = A.w - C[q].w;
            d2 += ex*ex + ey*ey + ez*ez + ew*ew;
            tn += U.x*V[q].x + U.y*V[q].y + U.z*V[q].z + U.w*V[q].w;
            uu += U.x*U.x + U.y*U.y + U.z*U.z + U.w*U.w;
        }
        #pragma unroll
        for (int off = 1; off < 8; off <<= 1) {
            d2 += __shfl_xor_sync(FULL, d2, off);
            tn += __shfl_xor_sync(FULL, tn, off);
            uu += __shfl_xor_sync(FULL, uu, off);
        }

        // vsim for this subgroup's agent: lives on lane ((cc&7)*4 + sg)
        float vsrc = (cc < 8) ? vs_lo : vs_hi;
        float vs = __shfl_sync(FULL, vsrc, ((cc & 7) << 2) + sg);

        float tsim  = tn / (fmaxf(sqrtf(uu), 1e-8f) * vnm);
        float score = 0.3f * sqrtf(d2)
                    + 0.5f * (1.0f - fmaxf(vs,   0.0f))
                    + 0.4f * (1.0f - fmaxf(tsim, 0.0f));
        score = fmaxf(score, 0.0f);   // keep bit-pattern order-preserving

        // collector: lane with (l>>2)==(cc&7) stores subgroup (l&3)'s key
        float sc = __shfl_sync(FULL, score, (l & 3) << 3);
        const int jc = j0 + cc * 32 + w * 4 + (l & 3);
        if ((l >> 2) == (cc & 7) && jc < NN) {
            unsigned long long key =
                ((unsigned long long)__float_as_uint(sc) << 32)
                | (unsigned int)(jc - 1);
            if (cc < 8) k0 = key; else k1 = key;
        }

        __syncthreads();   // buffer (cc+2)%3's previous consumers are done
        if (cc + 2 < NSTAGE) issue(cc + 2);
    }

    // ---- warp top-8 over 64 keys (2 per lane) ----
    unsigned long long sel = KEY_MAX;
    #pragma unroll
    for (int it = 0; it < KK; it++) {
        unsigned long long m = umin64(k0, k1);
        #pragma unroll
        for (int off = 16; off > 0; off >>= 1)
            m = umin64(m, __shfl_xor_sync(FULL, m, off));
        if (k0 == m) k0 = KEY_MAX;
        else if (k1 == m) k1 = KEY_MAX;
        if (l == it) sel = m;
    }
    if (l < KK) skeys[w * KK + l] = sel;
    __syncthreads();

    // ---- block merge: warp 0 reduces 64 -> 8, writes candidates ----
    if (w == 0) {
        unsigned long long a0 = skeys[l];
        unsigned long long a1 = skeys[l + 32];
        unsigned long long sel2 = KEY_MAX;
        #pragma unroll
        for (int it = 0; it < KK; it++) {
            unsigned long long m = umin64(a0, a1);
            #pragma unroll
            for (int off = 16; off > 0; off >>= 1)
                m = umin64(m, __shfl_xor_sync(FULL, m, off));
            if (a0 == m) a0 = KEY_MAX;
            else if (a1 == m) a1 = KEY_MAX;
            if (l == it) sel2 = m;
        }
        if (l < KK)
            cand[(size_t)b * CANDS + blk * KK + l] = sel2;
    }

    // ---- arrival protocol: last block of this batch merges + gathers ----
    __threadfence();
    __syncthreads();
    if (t == 0) {
        int old = atomicAdd(&g_counter[b], 1);
        s_last = (old == BLKS_PER_B - 1) ? 1 : 0;
    }
    __syncthreads();
    if (!s_last) return;

    __threadfence();   // acquire: see all other blocks' cand writes

    if (t < 32) {
        unsigned long long q0 = cand[(size_t)b * CANDS + t];
        unsigned long long q1 = cand[(size_t)b * CANDS + 32 + t];
        #pragma unroll
        for (int it = 0; it < KK; it++) {
            unsigned long long m = umin64(q0, q1);
            #pragma unroll
            for (int off = 16; off > 0; off >>= 1)
                m = umin64(m, __shfl_xor_sync(FULL, m, off));
            if (q0 == m) q0 = KEY_MAX;
            else if (q1 == m) q1 = KEY_MAX;
            if (t == 0) sel_idx[it] = (int)(unsigned int)(m & 0xFFFFFFFFu);
        }
        if (t == 0) g_counter[b] = 0;   // reset for next graph replay
    }
    __syncthreads();

    // gather: 256 threads = 8 rows x 32 lanes of float4
    {
        const int kk  = t >> 5;
        const int idx = sel_idx[kk];
        float4 val = xb4[(size_t)(idx + 1) * 32 + l];
        ((float4*)(out + ((size_t)b * KK + kk) * FDIM))[l] = val;
    }
    if (t < KK)
        out[(size_t)BB * KK * FDIM + b * KK + t] = (float)sel_idx[t];
}

extern "C" void kernel_launch(void* const* d_in, const int* in_sizes, int n_in,
                              void* d_out, int out_size)
{
    const float* x  = (const float*)d_in[0];   // (B, N, FDIM) f32
    const float* hf = (const float*)d_in[1];   // (B, N, L, DH) f32
    const float* he = (const float*)d_in[2];   // (B, N, FDIM) f32
    float* out = (float*)d_out;

    unsigned long long* cand;
    cudaGetSymbolAddress((void**)&cand, g_cand);

    cudaFuncSetAttribute(fused_kernel,
                         cudaFuncAttributeMaxDynamicSharedMemorySize, SMEM_BYTES);

    fused_kernel<<<BB * BLKS_PER_B, THREADS, SMEM_BYTES>>>(x, hf, he, cand, out);
}